// round 15
// baseline (speedup 1.0000x reference)
#include <cuda_runtime.h>
#include <cuda_fp16.h>
#include <cstdint>

#define BB 2
#define NN 512
#define HH 64
#define NODES (BB*NN)
#define JT 128
#define NTILES (NN/JT)

// ---------------- scratch (device globals) -------------------------------------
__device__ float g_h[NODES*HH];
__device__ float g_a[2][NODES*HH];        // ping-pong by layer parity
__device__ float g_ct[2][BB*HH*NN];       // c_j, n-major: [b][n][j]
__device__ float g_fsum[NODES*2];
__device__ __half g_wh[3][4][HH*HH];      // per layer: W2hi,W2lo,F1hi,F1lo (swizzled [k][n])

// ---------------- helpers -------------------------------------------------------
__device__ __forceinline__ float silu_f(float x){
    float t;
    asm("tanh.approx.f32 %0, %1;" : "=f"(t) : "f"(x * 0.5f));
    return 0.5f * x * (1.0f + t);
}
__device__ __forceinline__ float silu_x(float x){
    float e = __expf(-x);
    return x * __fdividef(1.0f, 1.0f + e);
}
// packed fp16x2 silu: returns silu(p0),silu(p1) as packed halves
__device__ __forceinline__ uint32_t silu_h2(float p0, float p1){
    __half2 x  = __floats2half2_rn(p0, p1);
    __half2 xh = __hmul2(x, __float2half2_rn(0.5f));
    uint32_t xi = *(uint32_t*)&xh, ti;
    asm("tanh.approx.f16x2 %0, %1;" : "=r"(ti) : "r"(xi));
    __half2 th = *(__half2*)&ti;
    __half2 r  = __hfma2(xh, th, xh);     // (x/2)(1+tanh(x/2)) = silu(x)
    return *(uint32_t*)&r;
}
__device__ __forceinline__ uint32_t sw128(uint32_t b){ return b ^ ((b >> 3) & 0x70); }

__device__ __forceinline__ void ldsm4(uint32_t& r0, uint32_t& r1, uint32_t& r2, uint32_t& r3, uint32_t a){
    asm volatile("ldmatrix.sync.aligned.m8n8.x4.shared.b16 {%0,%1,%2,%3}, [%4];"
                 : "=r"(r0), "=r"(r1), "=r"(r2), "=r"(r3) : "r"(a));
}
__device__ __forceinline__ void ldsm4t(uint32_t& r0, uint32_t& r1, uint32_t& r2, uint32_t& r3, uint32_t a){
    asm volatile("ldmatrix.sync.aligned.m8n8.x4.trans.shared.b16 {%0,%1,%2,%3}, [%4];"
                 : "=r"(r0), "=r"(r1), "=r"(r2), "=r"(r3) : "r"(a));
}
__device__ __forceinline__ void mma16816(float* d, uint32_t a0, uint32_t a1, uint32_t a2, uint32_t a3,
                                         uint32_t b0, uint32_t b1){
    asm volatile("mma.sync.aligned.m16n8k16.row.col.f32.f16.f16.f32 "
                 "{%0,%1,%2,%3},{%4,%5,%6,%7},{%8,%9},{%0,%1,%2,%3};"
                 : "+f"(d[0]), "+f"(d[1]), "+f"(d[2]), "+f"(d[3])
                 : "r"(a0), "r"(a1), "r"(a2), "r"(a3), "r"(b0), "r"(b1));
}
__device__ __forceinline__ uint32_t smem_u32(const void* p){
    uint32_t a;
    asm("{ .reg .u64 t; cvta.to.shared.u64 t, %1; cvt.u32.u64 %0, t; }" : "=r"(a) : "l"(p));
    return a;
}

// m32xn32 warp-tiled GEMM with W-lo compensation:
// D[128x64] += T @ (Wh + Wl). Warp (wm,wn): rows wm*32..+31, cols wn*32..+31.
__device__ __forceinline__ void gemm_mma(uint32_t Th, uint32_t Wh, uint32_t Wl,
                                         int wm, int wn, int lane, float acc[8][4]){
    int rA0   = wm*32 + (lane & 7) + ((lane >> 3) & 1) * 8;
    int colA8 = ((lane >> 4) & 1) * 8;
    int krB   = (lane & 7) + ((lane >> 3) & 1) * 8;
    int ncB8  = ((lane >> 4) & 1) * 8;
    #pragma unroll
    for (int kk = 0; kk < 4; ++kk){
        uint32_t a0[4], a1[4];
        ldsm4(a0[0],a0[1],a0[2],a0[3],
              Th + sw128((uint32_t)(rA0*128 + (kk*16 + colA8)*2)));
        ldsm4(a1[0],a1[1],a1[2],a1[3],
              Th + sw128((uint32_t)((rA0+16)*128 + (kk*16 + colA8)*2)));
        #pragma unroll
        for (int nt16 = 0; nt16 < 2; ++nt16){
            uint32_t boff = sw128((uint32_t)((kk*16 + krB)*128 + (wn*32 + nt16*16 + ncB8)*2));
            uint32_t bh[4], bl[4];
            ldsm4t(bh[0],bh[1],bh[2],bh[3], Wh + boff);
            ldsm4t(bl[0],bl[1],bl[2],bl[3], Wl + boff);
            int n0 = nt16*2;
            mma16816(acc[0*4+n0],   a0[0],a0[1],a0[2],a0[3], bh[0],bh[1]);
            mma16816(acc[0*4+n0+1], a0[0],a0[1],a0[2],a0[3], bh[2],bh[3]);
            mma16816(acc[1*4+n0],   a1[0],a1[1],a1[2],a1[3], bh[0],bh[1]);
            mma16816(acc[1*4+n0+1], a1[0],a1[1],a1[2],a1[3], bh[2],bh[3]);
            mma16816(acc[0*4+n0],   a0[0],a0[1],a0[2],a0[3], bl[0],bl[1]);
            mma16816(acc[0*4+n0+1], a0[0],a0[1],a0[2],a0[3], bl[2],bl[3]);
            mma16816(acc[1*4+n0],   a1[0],a1[1],a1[2],a1[3], bl[0],bl[1]);
            mma16816(acc[1*4+n0+1], a1[0],a1[1],a1[2],a1[3], bl[2],bl[3]);
        }
    }
}

// ---------------- weight prep: fp16 hi/lo split + SW128 swizzle -------------------
__global__ void k_wprep(const float* __restrict__ ew2, const float* __restrict__ fw1){
    int l = blockIdx.x >> 1, mat = blockIdx.x & 1;
    const float* src = (mat == 0) ? (ew2 + l*HH*HH) : (fw1 + l*HH*HH);
    __half* dh = g_wh[l][mat*2];
    __half* dl = g_wh[l][mat*2 + 1];
    for (int e = threadIdx.x; e < HH*HH; e += blockDim.x){
        float v = src[e];
        __half hh = __float2half_rn(v);
        __half hl = __float2half_rn(v - __half2float(hh));
        uint32_t sw = sw128((uint32_t)((e >> 6)*128 + (e & 63)*2));
        dh[sw >> 1] = hh;
        dl[sw >> 1] = hl;
    }
}

// ---------------- fused: h init + layer-0 prep (writes buffer 0) ------------------
__global__ void k_pre(const float* __restrict__ state,
                      const float* __restrict__ hw, const float* __restrict__ hb,
                      const float* __restrict__ ew1l, const float* __restrict__ eb1l){
    __shared__ float hs[HH];
    int node = blockIdx.x; int t = threadIdx.x;
    float4 st = ((const float4*)state)[node];
    float spd = sqrtf(st.z*st.z + st.w*st.w);
    float h = silu_x(spd * hw[t] + hb[t]);
    g_h[node*HH + t] = h;
    hs[t] = h;
    __syncthreads();
    float a = eb1l[t], c = 0.f;
    #pragma unroll 8
    for (int k = 0; k < HH; ++k){
        float hv = hs[k];
        a = fmaf(hv, ew1l[k*HH + t],        a);
        c = fmaf(hv, ew1l[(HH + k)*HH + t], c);
    }
    g_a[0][node*HH + t] = a;
    int b = node >> 9, j = node & (NN - 1);
    g_ct[0][(b*HH + t)*NN + j] = c;
}

// ---------------- edge smem -------------------------------------------------------
struct EdgeSmem {
    __half T1h[2][JT*HH];            // 32KB, double-buffered (aliased by MLP tail)
    __half T2h[JT*HH];               // 16KB
    __half WB[4][HH*HH];             // W2h, W2l, F1h, F1l : 8KB each
    float  A[HH];
    float4 WS[HH];
    float  B2[HH], FB1[HH], FW2[HH];
    float  Fw[2][JT];                // per-row fw sums, tile-parity buffered
    float  Magg[HH], T2i[HH], Fxy[2];
};

// ---------------- edge kernel: pipelined, CTA=(b,i), 256 thr ----------------------
__global__ void __launch_bounds__(256, 2) k_edge(
    const float* __restrict__ state,
    const float* __restrict__ ew1l,
    const float* __restrict__ eb2l,
    const float* __restrict__ fb1l,
    const float* __restrict__ fw2l,
    const float* __restrict__ fb2l,
    const float* __restrict__ nw1l,
    const float* __restrict__ nb1l,
    const float* __restrict__ nw2l,
    const float* __restrict__ nb2l,
    const float* __restrict__ ew1n,
    const float* __restrict__ eb1n,
    int layer, int accumulate, int prep_next)
{
    extern __shared__ __align__(16) char smem_raw[];
    EdgeSmem& s = *reinterpret_cast<EdgeSmem*>(smem_raw);

    int tid  = threadIdx.x;
    int wid  = tid >> 5;
    int lane = tid & 31;
    int wm   = wid & 3;
    int wn   = wid >> 2;
    int bi   = blockIdx.x;
    int b    = bi >> 9;
    int i    = bi & (NN - 1);
    int rb   = layer & 1;

    {   // stage weights (32KB flat, coalesced)
        const float4* src = (const float4*)g_wh[layer][0];
        float4* dst = (float4*)s.WB[0];
        #pragma unroll
        for (int q = 0; q < 8; ++q) dst[tid + 256*q] = src[tid + 256*q];
    }
    if (tid < HH){
        s.A[tid]   = g_a[rb][bi*HH + tid];
        s.WS[tid]  = make_float4(ew1l[128*HH + tid], ew1l[129*HH + tid],
                                 ew1l[130*HH + tid], ew1l[131*HH + tid]);
        s.B2[tid]  = eb2l[tid];
        s.FB1[tid] = fb1l[tid];
        s.FW2[tid] = fw2l[tid];
        s.Magg[tid] = 0.0f;
        s.T2i[tid]  = 0.0f;
    }
    ((float*)s.Fw)[tid] = 0.0f;
    if (tid < 2) s.Fxy[tid] = 0.0f;

    uint32_t aT1[2] = { smem_u32(s.T1h[0]), smem_u32(s.T1h[1]) };
    uint32_t aT2h = smem_u32(s.T2h);
    uint32_t aW2h = smem_u32(s.WB[0]), aW2l = smem_u32(s.WB[1]);
    uint32_t aF1h = smem_u32(s.WB[2]), aF1l = smem_u32(s.WB[3]);

    float4 sti = ((const float4*)state)[b*NN + i];
    float spi  = sti.z*sti.z + sti.w*sti.w;
    float fb2v = fb2l[0];
    int jt_i = i >> 7, r_i = i & (JT - 1);

    float fx = 0.f, fy = 0.f;
    float pnx0 = 0.f, pny0 = 0.f, pnx1 = 0.f, pny1 = 0.f;  // normals per parity
    float cs[8];
    #pragma unroll
    for (int q = 0; q < 8; ++q) cs[q] = 0.f;

    // stage0 for tile `jtile` -> T1h[jtile&1]; records this thread's normal
    auto stage0 = [&](int jtile){
        int jr = tid & (JT - 1);
        int half = tid >> 7;
        int j = jtile*JT + jr;
        float4 stj = ((const float4*)state)[b*NN + j];
        float dxp = stj.x - sti.x;
        float dyp = stj.y - sti.y;
        float dsq = dxp*dxp + dyp*dyp;
        float invd = rsqrtf(dsq + 1e-8f);
        float nx = dxp * invd;
        float ny = dyp * invd;
        float dvx = stj.z - sti.z;
        float dvy = stj.w - sti.w;
        float spj = stj.z*stj.z + stj.w*stj.w;
        float appr = dvx*nx + dvy*ny;
        if (half == 0){
            if (jtile & 1){ pnx1 = nx; pny1 = ny; }
            else          { pnx0 = nx; pny0 = ny; }
        }
        __half* T1d = s.T1h[jtile & 1];
        uint32_t hibuf[16];
        #pragma unroll
        for (int q = 0; q < 16; ++q){
            float pv[2];
            #pragma unroll
            for (int e = 0; e < 2; ++e){
                int n = half*32 + q*2 + e;
                float c = g_ct[rb][(b*HH + n)*NN + j];
                float4 w = s.WS[n];
                float p = s.A[n] + c;
                p = fmaf(dsq,  w.x, p);
                p = fmaf(spi,  w.y, p);
                p = fmaf(spj,  w.z, p);
                p = fmaf(appr, w.w, p);
                pv[e] = p;
            }
            hibuf[q] = silu_h2(pv[0], pv[1]);
        }
        #pragma unroll
        for (int c = 0; c < 4; ++c){
            uint32_t cc = (uint32_t)(half*4 + c);
            uint32_t off = (uint32_t)(jr*128) + ((cc ^ (uint32_t)(jr & 7)) << 4);
            *(uint4*)((char*)T1d + off) =
                make_uint4(hibuf[c*4], hibuf[c*4+1], hibuf[c*4+2], hibuf[c*4+3]);
        }
    };

    // fold tile with parity p into force accumulators, zero its Fw buffer
    auto fold = [&](int p){
        if (tid < JT){
            float fwv = s.Fw[p][tid] + fb2v;
            float nx = p ? pnx1 : pnx0;
            float ny = p ? pny1 : pny0;
            fx = fmaf(fwv, nx, fx);        // normal==0 at j==i -> auto-masked
            fy = fmaf(fwv, ny, fy);
            s.Fw[p][tid] = 0.0f;
        }
    };

    __syncthreads();   // (INIT)
    stage0(0);

    #pragma unroll 1
    for (int jt = 0; jt < NTILES; ++jt){
        int pb = jt & 1;
        __syncthreads();   // (A) T1[pb] ready; prev epi2 atomics + T2 reads done
        if (jt > 0) fold(pb ^ 1);

        // ================= GEMM1: D1 = T1 @ (W2h + W2l) ==========================
        float acc[8][4];
        #pragma unroll
        for (int q = 0; q < 8; ++q)
            #pragma unroll
            for (int p = 0; p < 4; ++p) acc[q][p] = 0.f;
        gemm_mma(aT1[pb], aW2h, aW2l, wm, wn, lane, acc);

        // ---- epilogue1: silu(+b2) f32, magg partials, ->T2 fp16 ----
        #pragma unroll
        for (int mt = 0; mt < 2; ++mt){
            #pragma unroll
            for (int nt = 0; nt < 4; ++nt){
                int idx = mt*4 + nt;
                int c0 = wn*32 + nt*8 + (lane & 3)*2;
                float b2a = s.B2[c0], b2b = s.B2[c0+1];
                float v00 = silu_f(acc[idx][0] + b2a);
                float v01 = silu_f(acc[idx][1] + b2b);
                float v10 = silu_f(acc[idx][2] + b2a);
                float v11 = silu_f(acc[idx][3] + b2b);
                cs[nt*2]   += v00 + v10;
                cs[nt*2+1] += v01 + v11;
                int mg0 = wm*32 + mt*16 + (lane >> 2);
                int mg1 = mg0 + 8;
                *(__half2*)((char*)s.T2h + sw128((uint32_t)(mg0*128 + c0*2))) =
                    __floats2half2_rn(v00, v01);
                *(__half2*)((char*)s.T2h + sw128((uint32_t)(mg1*128 + c0*2))) =
                    __floats2half2_rn(v10, v11);
            }
        }
        __syncthreads();   // (B) T2 ready

        // ---- capture T2 row i (magg self-term) ----
        if (jt == jt_i && tid < 32){
            uint32_t o = sw128((uint32_t)(r_i*128 + tid*4));
            uint32_t hv = *(const uint32_t*)((const char*)s.T2h + o);
            s.T2i[tid*2]     = __half2float(__ushort_as_half((unsigned short)(hv & 0xffff)));
            s.T2i[tid*2 + 1] = __half2float(__ushort_as_half((unsigned short)(hv >> 16)));
        }

        // ---- pipelined stage0 of next tile (overlaps GEMM2) ----
        if (jt + 1 < NTILES) stage0(jt + 1);

        // ================= GEMM2: D2 = T2 @ (F1h + F1l) ==========================
        #pragma unroll
        for (int q = 0; q < 8; ++q)
            #pragma unroll
            for (int p = 0; p < 4; ++p) acc[q][p] = 0.f;
        gemm_mma(aT2h, aF1h, aF1l, wm, wn, lane, acc);

        // ---- epilogue2: per-row partial of silu(D2+fb1).fw2 -> Fw[pb] ----
        #pragma unroll
        for (int mt = 0; mt < 2; ++mt){
            float rp0 = 0.f, rp1 = 0.f;
            #pragma unroll
            for (int nt = 0; nt < 4; ++nt){
                int idx = mt*4 + nt;
                int c0 = wn*32 + nt*8 + (lane & 3)*2;
                float fa = s.FB1[c0], fb = s.FB1[c0+1];
                float wa = s.FW2[c0], wb = s.FW2[c0+1];
                rp0 = fmaf(silu_f(acc[idx][0] + fa), wa, rp0);
                rp0 = fmaf(silu_f(acc[idx][1] + fb), wb, rp0);
                rp1 = fmaf(silu_f(acc[idx][2] + fa), wa, rp1);
                rp1 = fmaf(silu_f(acc[idx][3] + fb), wb, rp1);
            }
            rp0 += __shfl_xor_sync(0xffffffffu, rp0, 1);
            rp0 += __shfl_xor_sync(0xffffffffu, rp0, 2);
            rp1 += __shfl_xor_sync(0xffffffffu, rp1, 1);
            rp1 += __shfl_xor_sync(0xffffffffu, rp1, 2);
            if ((lane & 3) == 0){
                int mg0 = wm*32 + mt*16 + (lane >> 2);
                atomicAdd(&s.Fw[pb][mg0],     rp0);
                atomicAdd(&s.Fw[pb][mg0 + 8], rp1);
            }
        }
    }

    __syncthreads();       // epi2(last) atomics complete
    fold(1);               // last tile (3) has parity 1

    // ---- final m_agg reduction ----
    #pragma unroll
    for (int nt = 0; nt < 4; ++nt){
        float s0 = cs[nt*2], s1 = cs[nt*2+1];
        s0 += __shfl_xor_sync(0xffffffffu, s0, 4);
        s0 += __shfl_xor_sync(0xffffffffu, s0, 8);
        s0 += __shfl_xor_sync(0xffffffffu, s0, 16);
        s1 += __shfl_xor_sync(0xffffffffu, s1, 4);
        s1 += __shfl_xor_sync(0xffffffffu, s1, 8);
        s1 += __shfl_xor_sync(0xffffffffu, s1, 16);
        if (lane < 4){
            int c0 = wn*32 + nt*8 + lane*2;
            atomicAdd(&s.Magg[c0],     s0);
            atomicAdd(&s.Magg[c0 + 1], s1);
        }
    }
    // ---- reduce forces ----
    fx += __shfl_xor_sync(0xffffffffu, fx, 16);
    fx += __shfl_xor_sync(0xffffffffu, fx, 8);
    fx += __shfl_xor_sync(0xffffffffu, fx, 4);
    fx += __shfl_xor_sync(0xffffffffu, fx, 2);
    fx += __shfl_xor_sync(0xffffffffu, fx, 1);
    fy += __shfl_xor_sync(0xffffffffu, fy, 16);
    fy += __shfl_xor_sync(0xffffffffu, fy, 8);
    fy += __shfl_xor_sync(0xffffffffu, fy, 4);
    fy += __shfl_xor_sync(0xffffffffu, fy, 2);
    fy += __shfl_xor_sync(0xffffffffu, fy, 1);
    if (lane == 0){
        atomicAdd(&s.Fxy[0], fx);
        atomicAdd(&s.Fxy[1], fy);
    }
    __syncthreads();

    if (tid < 2){
        float v = s.Fxy[tid];
        if (accumulate) g_fsum[bi*2 + tid] += v;
        else            g_fsum[bi*2 + tid] = v;
    }

    // ================= fused node-update MLP =================
    float* sIn = (float*)s.T1h;
    float* sP  = sIn + 128;
    float* sY  = sP + 256;
    if (tid < 64)       sIn[tid] = g_h[bi*HH + tid];
    else if (tid < 128) sIn[tid] = s.Magg[tid - 64] - s.T2i[tid - 64];
    __syncthreads();
    {
        int out = tid & 63, chk = tid >> 6;
        float p = 0.f;
        #pragma unroll 8
        for (int k = 0; k < 32; ++k)
            p = fmaf(sIn[chk*32 + k], nw1l[(chk*32 + k)*HH + out], p);
        sP[tid] = p;
    }
    __syncthreads();
    if (tid < 64)
        sY[tid] = silu_x(sP[tid] + sP[tid+64] + sP[tid+128] + sP[tid+192] + nb1l[tid]);
    __syncthreads();
    {
        int out = tid & 63, chk = tid >> 6;
        float p = 0.f;
        #pragma unroll 8
        for (int k = 0; k < 16; ++k)
            p = fmaf(sY[chk*16 + k], nw2l[(chk*16 + k)*HH + out], p);
        sP[tid] = p;
    }
    __syncthreads();
    if (tid < 64){
        float hn = sP[tid] + sP[tid+64] + sP[tid+128] + sP[tid+192] + nb2l[tid];
        g_h[bi*HH + tid] = hn;
        sIn[tid] = hn;
    }
    __syncthreads();

    // ====== fused next-layer prep: writes rb^1 buffer ======
    if (prep_next && tid < 128){
        int out = tid & 63, which = tid >> 6;
        float a = which ? 0.f : eb1n[out];
        const float* w = ew1n + (which ? HH*HH : 0);
        #pragma unroll 8
        for (int k = 0; k < HH; ++k)
            a = fmaf(sIn[k], w[k*HH + out], a);
        if (which == 0) g_a[rb ^ 1][bi*HH + out] = a;
        else            g_ct[rb ^ 1][(b*HH + out)*NN + i] = a;
    }
}

// ---------------- wall MLP + output -----------------------------------------------
__global__ void k_final(const float* __restrict__ state,
                        const float* __restrict__ w1, const float* __restrict__ b1,
                        const float* __restrict__ w2, const float* __restrict__ b2,
                        const float* __restrict__ w3, const float* __restrict__ b3,
                        float* __restrict__ out){
    __shared__ float sH[HH + 4];
    __shared__ float sY[HH];
    __shared__ float sM[4];
    int node = blockIdx.x; int t = threadIdx.x;
    sH[t] = g_h[node*HH + t];
    if (t < 4){
        float4 st = ((const float4*)state)[node];
        float d = (t == 0) ? st.x : (t == 1) ? 1.0f - st.x
                : (t == 2) ? st.y : 1.0f - st.y;
        sH[HH + t] = d;
    }
    __syncthreads();
    float a1 = b1[t];
    #pragma unroll 4
    for (int k = 0; k < HH + 4; ++k) a1 = fmaf(sH[k], w1[k*HH + t], a1);
    sY[t] = silu_x(a1);
    __syncthreads();
    float a2 = b2[t];
    #pragma unroll 8
    for (int k = 0; k < HH; ++k) a2 = fmaf(sY[k], w2[k*HH + t], a2);
    __syncthreads();
    sY[t] = silu_x(a2);
    __syncthreads();
    if (t < 4){
        float m = b3[t];
        #pragma unroll 8
        for (int k = 0; k < HH; ++k) m = fmaf(sY[k], w3[k*4 + t], m);
        sM[t] = m;
    }
    __syncthreads();
    if (t < 2){
        float wf = (t == 0) ? (sM[0] - sM[1]) : (sM[2] - sM[3]);
        out[node*2 + t] = g_fsum[node*2 + t] + wf;
    }
}

// ---------------- launch ----------------------------------------------------------
extern "C" void kernel_launch(void* const* d_in, const int* in_sizes, int n_in,
                              void* d_out, int out_size){
    const float* state = (const float*)d_in[0];
    const float* hiw  = (const float*)d_in[1];
    const float* hib  = (const float*)d_in[2];
    const float* ew1  = (const float*)d_in[3];
    const float* eb1  = (const float*)d_in[4];
    const float* ew2  = (const float*)d_in[5];
    const float* eb2  = (const float*)d_in[6];
    const float* fw1  = (const float*)d_in[7];
    const float* fb1  = (const float*)d_in[8];
    const float* fw2  = (const float*)d_in[9];
    const float* fb2  = (const float*)d_in[10];
    const float* nw1  = (const float*)d_in[11];
    const float* nb1  = (const float*)d_in[12];
    const float* nw2  = (const float*)d_in[13];
    const float* nb2  = (const float*)d_in[14];
    const float* ww1  = (const float*)d_in[15];
    const float* wb1  = (const float*)d_in[16];
    const float* ww2  = (const float*)d_in[17];
    const float* wb2  = (const float*)d_in[18];
    const float* ww3  = (const float*)d_in[19];
    const float* wb3  = (const float*)d_in[20];
    float* out = (float*)d_out;

    int smem = (int)sizeof(EdgeSmem);
    cudaFuncSetAttribute(k_edge, cudaFuncAttributeMaxDynamicSharedMemorySize, smem);

    k_wprep<<<6, 256>>>(ew2, fw1);
    k_pre<<<NODES, HH>>>(state, hiw, hib, ew1, eb1);
    for (int l = 0; l < 3; ++l){
        int pn = (l < 2) ? 1 : 0;
        const float* ew1n = ew1 + (pn ? (l+1)*132*HH : 0);
        const float* eb1n = eb1 + (pn ? (l+1)*HH : 0);
        k_edge<<<NODES, 256, smem>>>(state,
                               ew1 + l*132*HH,
                               eb2 + l*HH,
                               fb1 + l*HH,
                               fw2 + l*HH,
                               fb2 + l,
                               nw1 + l*2*HH*HH, nb1 + l*HH,
                               nw2 + l*HH*HH,   nb2 + l*HH,
                               ew1n, eb1n,
                               l, l, pn);
    }
    k_final<<<NODES, HH>>>(state, ww1, wb1, ww2, wb2, ww3, wb3, out);
}

// round 16
// speedup vs baseline: 1.1571x; 1.1571x over previous
#include <cuda_runtime.h>
#include <cuda_fp16.h>
#include <cstdint>

#define BB 2
#define NN 512
#define HH 64
#define NODES (BB*NN)
#define JT 128
#define NTILES (NN/JT)

// ---------------- scratch (device globals) -------------------------------------
__device__ float g_h[NODES*HH];
__device__ float g_a[2][NODES*HH];        // ping-pong by layer parity
__device__ float g_ct[2][BB*HH*NN];       // c_j, n-major: [b][n][j]
__device__ float g_fsum[NODES*2];
__device__ __half g_wh[3][3][HH*HH];      // per layer: W2hi, W2lo, F1 (swizzled [k][n])

// ---------------- helpers -------------------------------------------------------
__device__ __forceinline__ float silu_f(float x){
    float t;
    asm("tanh.approx.f32 %0, %1;" : "=f"(t) : "f"(x * 0.5f));
    return 0.5f * x * (1.0f + t);
}
__device__ __forceinline__ float silu_x(float x){
    float e = __expf(-x);
    return x * __fdividef(1.0f, 1.0f + e);
}
__device__ __forceinline__ uint32_t sw128(uint32_t b){ return b ^ ((b >> 3) & 0x70); }
__device__ __forceinline__ uint32_t packh2(float a, float b){
    __half2 h = __floats2half2_rn(a, b);
    return *(uint32_t*)&h;
}
__device__ __forceinline__ void ldsm4(uint32_t& r0, uint32_t& r1, uint32_t& r2, uint32_t& r3, uint32_t a){
    asm volatile("ldmatrix.sync.aligned.m8n8.x4.shared.b16 {%0,%1,%2,%3}, [%4];"
                 : "=r"(r0), "=r"(r1), "=r"(r2), "=r"(r3) : "r"(a));
}
__device__ __forceinline__ void ldsm4t(uint32_t& r0, uint32_t& r1, uint32_t& r2, uint32_t& r3, uint32_t a){
    asm volatile("ldmatrix.sync.aligned.m8n8.x4.trans.shared.b16 {%0,%1,%2,%3}, [%4];"
                 : "=r"(r0), "=r"(r1), "=r"(r2), "=r"(r3) : "r"(a));
}
__device__ __forceinline__ void mma16816(float* d, uint32_t a0, uint32_t a1, uint32_t a2, uint32_t a3,
                                         uint32_t b0, uint32_t b1){
    asm volatile("mma.sync.aligned.m16n8k16.row.col.f32.f16.f16.f32 "
                 "{%0,%1,%2,%3},{%4,%5,%6,%7},{%8,%9},{%0,%1,%2,%3};"
                 : "+f"(d[0]), "+f"(d[1]), "+f"(d[2]), "+f"(d[3])
                 : "r"(a0), "r"(a1), "r"(a2), "r"(a3), "r"(b0), "r"(b1));
}
__device__ __forceinline__ uint32_t smem_u32(const void* p){
    uint32_t a;
    asm("{ .reg .u64 t; cvta.to.shared.u64 t, %1; cvt.u32.u64 %0, t; }" : "=r"(a) : "l"(p));
    return a;
}

// GEMM1: D[128x64] += T @ (Wh + Wl). m16n64 warp tile (warp m0 = wid*16).
__device__ __forceinline__ void gemm1(uint32_t Th, uint32_t Wh, uint32_t Wl,
                                      int m0, int lane, float acc[8][4]){
    int rA    = m0 + (lane & 7) + ((lane >> 3) & 1) * 8;
    int colA8 = ((lane >> 4) & 1) * 8;
    int krB   = (lane & 7) + ((lane >> 3) & 1) * 8;
    int ncB8  = ((lane >> 4) & 1) * 8;
    #pragma unroll
    for (int kk = 0; kk < 4; ++kk){
        uint32_t a0, a1, a2, a3;
        ldsm4(a0, a1, a2, a3, Th + sw128((uint32_t)(rA*128 + (kk*16 + colA8)*2)));
        #pragma unroll
        for (int np = 0; np < 4; ++np){
            uint32_t boff = sw128((uint32_t)((kk*16 + krB)*128 + (np*16 + ncB8)*2));
            uint32_t bh0, bh1, bh2, bh3, bl0, bl1, bl2, bl3;
            ldsm4t(bh0, bh1, bh2, bh3, Wh + boff);
            ldsm4t(bl0, bl1, bl2, bl3, Wl + boff);
            mma16816(acc[np*2],   a0, a1, a2, a3, bh0, bh1);
            mma16816(acc[np*2+1], a0, a1, a2, a3, bh2, bh3);
            mma16816(acc[np*2],   a0, a1, a2, a3, bl0, bl1);
            mma16816(acc[np*2+1], a0, a1, a2, a3, bl2, bl3);
        }
    }
}

// ---------------- weight prep ------------------------------------------------------
__global__ void k_wprep(const float* __restrict__ ew2, const float* __restrict__ fw1){
    int l = blockIdx.x >> 1, mat = blockIdx.x & 1;
    const float* src = (mat == 0) ? (ew2 + l*HH*HH) : (fw1 + l*HH*HH);
    for (int e = threadIdx.x; e < HH*HH; e += blockDim.x){
        float v = src[e];
        uint32_t sw = sw128((uint32_t)((e >> 6)*128 + (e & 63)*2)) >> 1;
        if (mat == 0){
            __half hh = __float2half_rn(v);
            g_wh[l][0][sw] = hh;
            g_wh[l][1][sw] = __float2half_rn(v - __half2float(hh));
        } else {
            g_wh[l][2][sw] = __float2half_rn(v);
        }
    }
}

// ---------------- fused: h init + layer-0 prep (writes buffer 0) ------------------
__global__ void k_pre(const float* __restrict__ state,
                      const float* __restrict__ hw, const float* __restrict__ hb,
                      const float* __restrict__ ew1l, const float* __restrict__ eb1l){
    __shared__ float hs[HH];
    int node = blockIdx.x; int t = threadIdx.x;
    float4 st = ((const float4*)state)[node];
    float spd = sqrtf(st.z*st.z + st.w*st.w);
    float h = silu_x(spd * hw[t] + hb[t]);
    g_h[node*HH + t] = h;
    hs[t] = h;
    __syncthreads();
    float a = eb1l[t], c = 0.f;
    #pragma unroll 8
    for (int k = 0; k < HH; ++k){
        float hv = hs[k];
        a = fmaf(hv, ew1l[k*HH + t],        a);
        c = fmaf(hv, ew1l[(HH + k)*HH + t], c);
    }
    g_a[0][node*HH + t] = a;
    int b = node >> 9, j = node & (NN - 1);
    g_ct[0][(b*HH + t)*NN + j] = c;
}

// ---------------- edge smem -------------------------------------------------------
struct EdgeSmem {
    __half T1h[2][JT*HH];            // 32KB, parity double-buffered (MLP tail aliases)
    __half WB[3][HH*HH];             // W2h, W2l, F1 : 8KB each
    float  A[HH];
    float4 WS[HH];
    float  B2[HH], FB1[HH], FW2[HH];
    float  Nx[2][JT], Ny[2][JT];     // parity buffered
    float  Magg[HH], T2i[HH], Fxy[2];
};

// ---------------- edge kernel: CTA=(b,i), 256 thr, 1 barrier/tile ------------------
__global__ void __launch_bounds__(256, 2) k_edge(
    const float* __restrict__ state,
    const float* __restrict__ ew1l,
    const float* __restrict__ eb2l,
    const float* __restrict__ fb1l,
    const float* __restrict__ fw2l,
    const float* __restrict__ fb2l,
    const float* __restrict__ nw1l,
    const float* __restrict__ nb1l,
    const float* __restrict__ nw2l,
    const float* __restrict__ nb2l,
    const float* __restrict__ ew1n,
    const float* __restrict__ eb1n,
    int layer, int accumulate, int prep_next)
{
    extern __shared__ __align__(16) char smem_raw[];
    EdgeSmem& s = *reinterpret_cast<EdgeSmem*>(smem_raw);

    int tid  = threadIdx.x;
    int wid  = tid >> 5;
    int lane = tid & 31;
    int bi   = blockIdx.x;
    int b    = bi >> 9;
    int i    = bi & (NN - 1);
    int m0   = wid * 16;
    int rb   = layer & 1;

    {   // stage weights (24KB flat, coalesced)
        const float4* src = (const float4*)g_wh[layer][0];
        float4* dst = (float4*)s.WB[0];
        #pragma unroll
        for (int q = 0; q < 6; ++q) dst[tid + 256*q] = src[tid + 256*q];
    }
    if (tid < HH){
        s.A[tid]   = g_a[rb][bi*HH + tid];
        s.WS[tid]  = make_float4(ew1l[128*HH + tid], ew1l[129*HH + tid],
                                 ew1l[130*HH + tid], ew1l[131*HH + tid]);
        s.B2[tid]  = eb2l[tid];
        s.FB1[tid] = fb1l[tid];
        s.FW2[tid] = fw2l[tid];
        s.Magg[tid] = 0.0f;
        s.T2i[tid]  = 0.0f;
    }
    if (tid < 2) s.Fxy[tid] = 0.0f;

    uint32_t aT1[2] = { smem_u32(s.T1h[0]), smem_u32(s.T1h[1]) };
    uint32_t aW2h = smem_u32(s.WB[0]), aW2l = smem_u32(s.WB[1]);
    uint32_t aF1  = smem_u32(s.WB[2]);

    float4 sti = ((const float4*)state)[b*NN + i];
    float spi  = sti.z*sti.z + sti.w*sti.w;
    float fb2v = fb2l[0];
    int jt_i = i >> 7, r_i = i & (JT - 1);

    float fx = 0.f, fy = 0.f;
    float cs[16];
    #pragma unroll
    for (int q = 0; q < 16; ++q) cs[q] = 0.f;

    // B-operand lane constants (for GEMM2 / GEMM1)
    int krB  = (lane & 7) + ((lane >> 3) & 1) * 8;
    int ncB8 = ((lane >> 4) & 1) * 8;

    __syncthreads();   // (INIT)

    #pragma unroll 1
    for (int jt = 0; jt < NTILES; ++jt){
        int pb = jt & 1;
        // ================= stage 0: T1 row j -> fp16 smem (parity buffer) ========
        {
            int jr = tid & (JT - 1);
            int half = tid >> 7;
            int j = jt*JT + jr;
            float4 stj = ((const float4*)state)[b*NN + j];
            float dxp = stj.x - sti.x;
            float dyp = stj.y - sti.y;
            float dsq = dxp*dxp + dyp*dyp;
            float invd = rsqrtf(dsq + 1e-8f);
            float nx = dxp * invd;
            float ny = dyp * invd;
            float dvx = stj.z - sti.z;
            float dvy = stj.w - sti.w;
            float spj = stj.z*stj.z + stj.w*stj.w;
            float appr = dvx*nx + dvy*ny;
            if (half == 0){ s.Nx[pb][jr] = nx; s.Ny[pb][jr] = ny; }

            __half* T1d = s.T1h[pb];
            uint32_t hibuf[16];
            #pragma unroll
            for (int q = 0; q < 16; ++q){
                float tv[2];
                #pragma unroll
                for (int e = 0; e < 2; ++e){
                    int n = half*32 + q*2 + e;
                    float c = g_ct[rb][(b*HH + n)*NN + j];
                    float4 w = s.WS[n];
                    float p = s.A[n] + c;
                    p = fmaf(dsq,  w.x, p);
                    p = fmaf(spi,  w.y, p);
                    p = fmaf(spj,  w.z, p);
                    p = fmaf(appr, w.w, p);
                    tv[e] = silu_f(p);
                }
                hibuf[q] = packh2(tv[0], tv[1]);
            }
            #pragma unroll
            for (int c = 0; c < 4; ++c){
                uint32_t cc = (uint32_t)(half*4 + c);
                uint32_t off = (uint32_t)(jr*128) + ((cc ^ (uint32_t)(jr & 7)) << 4);
                *(uint4*)((char*)T1d + off) =
                    make_uint4(hibuf[c*4], hibuf[c*4+1], hibuf[c*4+2], hibuf[c*4+3]);
            }
        }
        __syncthreads();   // (A) only barrier per tile

        // ================= GEMM1: D1 = T1 @ (W2h + W2l) ==========================
        float acc[8][4];
        #pragma unroll
        for (int q = 0; q < 8; ++q)
            #pragma unroll
            for (int p = 0; p < 4; ++p) acc[q][p] = 0.f;
        gemm1(aT1[pb], aW2h, aW2l, m0, lane, acc);

        // ---- epilogue1: silu(+b2) f32, colsums, pack A-frags for GEMM2 ----------
        uint32_t af[4][4];
        #pragma unroll
        for (int nt = 0; nt < 8; ++nt){
            int c0 = nt*8 + (lane & 3)*2;
            float b2a = s.B2[c0], b2b = s.B2[c0+1];
            float v00 = silu_f(acc[nt][0] + b2a);
            float v01 = silu_f(acc[nt][1] + b2b);
            float v10 = silu_f(acc[nt][2] + b2a);
            float v11 = silu_f(acc[nt][3] + b2b);
            cs[nt*2]   += v00 + v10;
            cs[nt*2+1] += v01 + v11;
            int kk = nt >> 1;
            if ((nt & 1) == 0){
                af[kk][0] = packh2(v00, v01);   // a0: row lane>>2,   k 0-7 of chunk
                af[kk][1] = packh2(v10, v11);   // a1: row lane>>2+8, k 0-7
            } else {
                af[kk][2] = packh2(v00, v01);   // a2: row lane>>2,   k 8-15
                af[kk][3] = packh2(v10, v11);   // a3: row lane>>2+8, k 8-15
            }
            // row-i capture (for magg self-term), straight from registers
            if (jt == jt_i && wid == (r_i >> 4)){
                int ri = r_i & 15;
                if (ri < 8){
                    if ((lane >> 2) == ri){ s.T2i[c0] = v00; s.T2i[c0+1] = v01; }
                } else {
                    if ((lane >> 2) == ri - 8){ s.T2i[c0] = v10; s.T2i[c0+1] = v11; }
                }
            }
        }

        // ================= GEMM2: D2 = T2(regs) @ F1 =============================
        #pragma unroll
        for (int q = 0; q < 8; ++q)
            #pragma unroll
            for (int p = 0; p < 4; ++p) acc[q][p] = 0.f;
        #pragma unroll
        for (int kk = 0; kk < 4; ++kk){
            #pragma unroll
            for (int np = 0; np < 4; ++np){
                uint32_t boff = sw128((uint32_t)((kk*16 + krB)*128 + (np*16 + ncB8)*2));
                uint32_t f0, f1, f2, f3;
                ldsm4t(f0, f1, f2, f3, aF1 + boff);
                mma16816(acc[np*2],   af[kk][0], af[kk][1], af[kk][2], af[kk][3], f0, f1);
                mma16816(acc[np*2+1], af[kk][0], af[kk][1], af[kk][2], af[kk][3], f2, f3);
            }
        }

        // ---- epilogue2: fw = silu(D2 + fb1) . fw2 + fb2; force -------------------
        float pm = 0.f, pm8 = 0.f;
        #pragma unroll
        for (int nt = 0; nt < 8; ++nt){
            int c0 = nt*8 + (lane & 3)*2;
            float fa = s.FB1[c0], fb = s.FB1[c0+1];
            float wa = s.FW2[c0], wb = s.FW2[c0+1];
            pm  = fmaf(silu_f(acc[nt][0] + fa), wa, pm);
            pm  = fmaf(silu_f(acc[nt][1] + fb), wb, pm);
            pm8 = fmaf(silu_f(acc[nt][2] + fa), wa, pm8);
            pm8 = fmaf(silu_f(acc[nt][3] + fb), wb, pm8);
        }
        pm  += __shfl_xor_sync(0xffffffffu, pm, 1);
        pm  += __shfl_xor_sync(0xffffffffu, pm, 2);
        pm8 += __shfl_xor_sync(0xffffffffu, pm8, 1);
        pm8 += __shfl_xor_sync(0xffffffffu, pm8, 2);
        if ((lane & 3) == 0){
            int r0_ = m0 + (lane >> 2);
            int r1_ = r0_ + 8;
            float f0 = pm + fb2v, f1 = pm8 + fb2v;
            fx = fmaf(f0, s.Nx[pb][r0_], fx); fx = fmaf(f1, s.Nx[pb][r1_], fx);
            fy = fmaf(f0, s.Ny[pb][r0_], fy); fy = fmaf(f1, s.Ny[pb][r1_], fy);
        }
        // no barrier: T1/Nx/Ny parity-buffered; next syncA orders reuse
    }

    // ---- final m_agg reduction ----
    #pragma unroll
    for (int nt = 0; nt < 8; ++nt){
        float s0 = cs[nt*2], s1 = cs[nt*2+1];
        s0 += __shfl_xor_sync(0xffffffffu, s0, 4);
        s0 += __shfl_xor_sync(0xffffffffu, s0, 8);
        s0 += __shfl_xor_sync(0xffffffffu, s0, 16);
        s1 += __shfl_xor_sync(0xffffffffu, s1, 4);
        s1 += __shfl_xor_sync(0xffffffffu, s1, 8);
        s1 += __shfl_xor_sync(0xffffffffu, s1, 16);
        if (lane < 4){
            int c0 = nt*8 + lane*2;
            atomicAdd(&s.Magg[c0],     s0);
            atomicAdd(&s.Magg[c0 + 1], s1);
        }
    }
    // ---- reduce forces (values live at lanes with lane&3==0) ----
    fx += __shfl_xor_sync(0xffffffffu, fx, 16);
    fx += __shfl_xor_sync(0xffffffffu, fx, 8);
    fx += __shfl_xor_sync(0xffffffffu, fx, 4);
    fy += __shfl_xor_sync(0xffffffffu, fy, 16);
    fy += __shfl_xor_sync(0xffffffffu, fy, 8);
    fy += __shfl_xor_sync(0xffffffffu, fy, 4);
    if (lane == 0){
        atomicAdd(&s.Fxy[0], fx);
        atomicAdd(&s.Fxy[1], fy);
    }
    __syncthreads();

    if (tid < 2){
        float v = s.Fxy[tid];
        if (accumulate) g_fsum[bi*2 + tid] += v;
        else            g_fsum[bi*2 + tid] = v;
    }

    // ================= fused node-update MLP =================
    float* sIn = (float*)s.T1h;
    float* sP  = sIn + 128;
    float* sY  = sP + 256;
    if (tid < 64)       sIn[tid] = g_h[bi*HH + tid];
    else if (tid < 128) sIn[tid] = s.Magg[tid - 64] - s.T2i[tid - 64];
    __syncthreads();
    {
        int out = tid & 63, chk = tid >> 6;
        float p = 0.f;
        #pragma unroll 8
        for (int k = 0; k < 32; ++k)
            p = fmaf(sIn[chk*32 + k], nw1l[(chk*32 + k)*HH + out], p);
        sP[tid] = p;
    }
    __syncthreads();
    if (tid < 64)
        sY[tid] = silu_x(sP[tid] + sP[tid+64] + sP[tid+128] + sP[tid+192] + nb1l[tid]);
    __syncthreads();
    {
        int out = tid & 63, chk = tid >> 6;
        float p = 0.f;
        #pragma unroll 8
        for (int k = 0; k < 16; ++k)
            p = fmaf(sY[chk*16 + k], nw2l[(chk*16 + k)*HH + out], p);
        sP[tid] = p;
    }
    __syncthreads();
    if (tid < 64){
        float hn = sP[tid] + sP[tid+64] + sP[tid+128] + sP[tid+192] + nb2l[tid];
        g_h[bi*HH + tid] = hn;
        sIn[tid] = hn;
    }
    __syncthreads();

    // ====== fused next-layer prep: writes rb^1 buffer ======
    if (prep_next && tid < 128){
        int out = tid & 63, which = tid >> 6;
        float a = which ? 0.f : eb1n[out];
        const float* w = ew1n + (which ? HH*HH : 0);
        #pragma unroll 8
        for (int k = 0; k < HH; ++k)
            a = fmaf(sIn[k], w[k*HH + out], a);
        if (which == 0) g_a[rb ^ 1][bi*HH + out] = a;
        else            g_ct[rb ^ 1][(b*HH + out)*NN + i] = a;
    }
}

// ---------------- wall MLP + output -----------------------------------------------
__global__ void k_final(const float* __restrict__ state,
                        const float* __restrict__ w1, const float* __restrict__ b1,
                        const float* __restrict__ w2, const float* __restrict__ b2,
                        const float* __restrict__ w3, const float* __restrict__ b3,
                        float* __restrict__ out){
    __shared__ float sH[HH + 4];
    __shared__ float sY[HH];
    __shared__ float sM[4];
    int node = blockIdx.x; int t = threadIdx.x;
    sH[t] = g_h[node*HH + t];
    if (t < 4){
        float4 st = ((const float4*)state)[node];
        float d = (t == 0) ? st.x : (t == 1) ? 1.0f - st.x
                : (t == 2) ? st.y : 1.0f - st.y;
        sH[HH + t] = d;
    }
    __syncthreads();
    float a1 = b1[t];
    #pragma unroll 4
    for (int k = 0; k < HH + 4; ++k) a1 = fmaf(sH[k], w1[k*HH + t], a1);
    sY[t] = silu_x(a1);
    __syncthreads();
    float a2 = b2[t];
    #pragma unroll 8
    for (int k = 0; k < HH; ++k) a2 = fmaf(sY[k], w2[k*HH + t], a2);
    __syncthreads();
    sY[t] = silu_x(a2);
    __syncthreads();
    if (t < 4){
        float m = b3[t];
        #pragma unroll 8
        for (int k = 0; k < HH; ++k) m = fmaf(sY[k], w3[k*4 + t], m);
        sM[t] = m;
    }
    __syncthreads();
    if (t < 2){
        float wf = (t == 0) ? (sM[0] - sM[1]) : (sM[2] - sM[3]);
        out[node*2 + t] = g_fsum[node*2 + t] + wf;
    }
}

// ---------------- launch ----------------------------------------------------------
extern "C" void kernel_launch(void* const* d_in, const int* in_sizes, int n_in,
                              void* d_out, int out_size){
    const float* state = (const float*)d_in[0];
    const float* hiw  = (const float*)d_in[1];
    const float* hib  = (const float*)d_in[2];
    const float* ew1  = (const float*)d_in[3];
    const float* eb1  = (const float*)d_in[4];
    const float* ew2  = (const float*)d_in[5];
    const float* eb2  = (const float*)d_in[6];
    const float* fw1  = (const float*)d_in[7];
    const float* fb1  = (const float*)d_in[8];
    const float* fw2  = (const float*)d_in[9];
    const float* fb2  = (const float*)d_in[10];
    const float* nw1  = (const float*)d_in[11];
    const float* nb1  = (const float*)d_in[12];
    const float* nw2  = (const float*)d_in[13];
    const float* nb2  = (const float*)d_in[14];
    const float* ww1  = (const float*)d_in[15];
    const float* wb1  = (const float*)d_in[16];
    const float* ww2  = (const float*)d_in[17];
    const float* wb2  = (const float*)d_in[18];
    const float* ww3  = (const float*)d_in[19];
    const float* wb3  = (const float*)d_in[20];
    float* out = (float*)d_out;

    int smem = (int)sizeof(EdgeSmem);
    cudaFuncSetAttribute(k_edge, cudaFuncAttributeMaxDynamicSharedMemorySize, smem);

    k_wprep<<<6, 256>>>(ew2, fw1);
    k_pre<<<NODES, HH>>>(state, hiw, hib, ew1, eb1);
    for (int l = 0; l < 3; ++l){
        int pn = (l < 2) ? 1 : 0;
        const float* ew1n = ew1 + (pn ? (l+1)*132*HH : 0);
        const float* eb1n = eb1 + (pn ? (l+1)*HH : 0);
        k_edge<<<NODES, 256, smem>>>(state,
                               ew1 + l*132*HH,
                               eb2 + l*HH,
                               fb1 + l*HH,
                               fw2 + l*HH,
                               fb2 + l,
                               nw1 + l*2*HH*HH, nb1 + l*HH,
                               nw2 + l*HH*HH,   nb2 + l*HH,
                               ew1n, eb1n,
                               l, l, pn);
    }
    k_final<<<NODES, HH>>>(state, ww1, wb1, ww2, wb2, ww3, wb3, out);
}

// round 17
// speedup vs baseline: 1.2135x; 1.0487x over previous
#include <cuda_runtime.h>
#include <cuda_fp16.h>
#include <cstdint>

#define BB 2
#define NN 512
#define HH 64
#define NODES (BB*NN)
#define JT 128
#define NTILES (NN/JT)

// ---------------- scratch (device globals) -------------------------------------
__device__ float g_h[NODES*HH];
__device__ float g_a[2][NODES*HH];        // ping-pong by layer parity
__device__ float g_ct[2][BB*HH*NN];       // c_j, n-major: [b][n][j]
__device__ float g_fsum[NODES*2];
__device__ __half g_wh[3][3][HH*HH];      // per layer: W2hi, W2lo, F1 (swizzled [k][n])

// ---------------- helpers -------------------------------------------------------
__device__ __forceinline__ float silu_f(float x){
    float t;
    asm("tanh.approx.f32 %0, %1;" : "=f"(t) : "f"(x * 0.5f));
    return 0.5f * x * (1.0f + t);
}
__device__ __forceinline__ float silu_x(float x){
    float e = __expf(-x);
    return x * __fdividef(1.0f, 1.0f + e);
}
__device__ __forceinline__ uint32_t sw128(uint32_t b){ return b ^ ((b >> 3) & 0x70); }
__device__ __forceinline__ uint32_t packh2(float a, float b){
    __half2 h = __floats2half2_rn(a, b);
    return *(uint32_t*)&h;
}
__device__ __forceinline__ void ldsm4(uint32_t& r0, uint32_t& r1, uint32_t& r2, uint32_t& r3, uint32_t a){
    asm volatile("ldmatrix.sync.aligned.m8n8.x4.shared.b16 {%0,%1,%2,%3}, [%4];"
                 : "=r"(r0), "=r"(r1), "=r"(r2), "=r"(r3) : "r"(a));
}
__device__ __forceinline__ void ldsm4t(uint32_t& r0, uint32_t& r1, uint32_t& r2, uint32_t& r3, uint32_t a){
    asm volatile("ldmatrix.sync.aligned.m8n8.x4.trans.shared.b16 {%0,%1,%2,%3}, [%4];"
                 : "=r"(r0), "=r"(r1), "=r"(r2), "=r"(r3) : "r"(a));
}
__device__ __forceinline__ void mma16816(float* d, uint32_t a0, uint32_t a1, uint32_t a2, uint32_t a3,
                                         uint32_t b0, uint32_t b1){
    asm volatile("mma.sync.aligned.m16n8k16.row.col.f32.f16.f16.f32 "
                 "{%0,%1,%2,%3},{%4,%5,%6,%7},{%8,%9},{%0,%1,%2,%3};"
                 : "+f"(d[0]), "+f"(d[1]), "+f"(d[2]), "+f"(d[3])
                 : "r"(a0), "r"(a1), "r"(a2), "r"(a3), "r"(b0), "r"(b1));
}
__device__ __forceinline__ uint32_t smem_u32(const void* p){
    uint32_t a;
    asm("{ .reg .u64 t; cvta.to.shared.u64 t, %1; cvt.u32.u64 %0, t; }" : "=r"(a) : "l"(p));
    return a;
}

// ---------------- weight prep ------------------------------------------------------
__global__ void k_wprep(const float* __restrict__ ew2, const float* __restrict__ fw1){
    int l = blockIdx.x >> 1, mat = blockIdx.x & 1;
    const float* src = (mat == 0) ? (ew2 + l*HH*HH) : (fw1 + l*HH*HH);
    for (int e = threadIdx.x; e < HH*HH; e += blockDim.x){
        float v = src[e];
        uint32_t sw = sw128((uint32_t)((e >> 6)*128 + (e & 63)*2)) >> 1;
        if (mat == 0){
            __half hh = __float2half_rn(v);
            g_wh[l][0][sw] = hh;
            g_wh[l][1][sw] = __float2half_rn(v - __half2float(hh));
        } else {
            g_wh[l][2][sw] = __float2half_rn(v);
        }
    }
}

// ---------------- fused: h init + layer-0 prep (writes buffer 0) ------------------
__global__ void k_pre(const float* __restrict__ state,
                      const float* __restrict__ hw, const float* __restrict__ hb,
                      const float* __restrict__ ew1l, const float* __restrict__ eb1l){
    __shared__ float hs[HH];
    int node = blockIdx.x; int t = threadIdx.x;
    float4 st = ((const float4*)state)[node];
    float spd = sqrtf(st.z*st.z + st.w*st.w);
    float h = silu_x(spd * hw[t] + hb[t]);
    g_h[node*HH + t] = h;
    hs[t] = h;
    __syncthreads();
    float a = eb1l[t], c = 0.f;
    #pragma unroll 8
    for (int k = 0; k < HH; ++k){
        float hv = hs[k];
        a = fmaf(hv, ew1l[k*HH + t],        a);
        c = fmaf(hv, ew1l[(HH + k)*HH + t], c);
    }
    g_a[0][node*HH + t] = a;
    int b = node >> 9, j = node & (NN - 1);
    g_ct[0][(b*HH + t)*NN + j] = c;
}

// ---------------- edge smem -------------------------------------------------------
struct EdgeSmem {
    __half T1h[2][JT*HH];            // 32KB, parity double-buffered (MLP tail aliases)
    __half WB[3][HH*HH];             // W2h, W2l, F1 : 8KB each
    float  A[HH];
    float4 WS[HH];
    float  B2[HH], FB1[HH], FW2[HH];
    float  Nx[2][JT], Ny[2][JT];     // parity buffered
    float  Magg[HH], T2i[HH], Fxy[2];
};

// ---------------- edge kernel: CTA=(b,i), 128 thr, m32n64 warp tiles ---------------
__global__ void __launch_bounds__(128, 3) k_edge(
    const float* __restrict__ state,
    const float* __restrict__ ew1l,
    const float* __restrict__ eb2l,
    const float* __restrict__ fb1l,
    const float* __restrict__ fw2l,
    const float* __restrict__ fb2l,
    const float* __restrict__ nw1l,
    const float* __restrict__ nb1l,
    const float* __restrict__ nw2l,
    const float* __restrict__ nb2l,
    const float* __restrict__ ew1n,
    const float* __restrict__ eb1n,
    int layer, int accumulate, int prep_next)
{
    extern __shared__ __align__(16) char smem_raw[];
    EdgeSmem& s = *reinterpret_cast<EdgeSmem*>(smem_raw);

    int tid  = threadIdx.x;
    int wm   = tid >> 5;             // warp = m-group: rows wm*32..+31
    int lane = tid & 31;
    int bi   = blockIdx.x;
    int b    = bi >> 9;
    int i    = bi & (NN - 1);
    int rb   = layer & 1;

    {   // stage weights (24KB flat, coalesced)
        const float4* src = (const float4*)g_wh[layer][0];
        float4* dst = (float4*)s.WB[0];
        #pragma unroll
        for (int q = 0; q < 12; ++q) dst[tid + 128*q] = src[tid + 128*q];
    }
    if (tid < HH){
        s.A[tid]   = g_a[rb][bi*HH + tid];
        s.WS[tid]  = make_float4(ew1l[128*HH + tid], ew1l[129*HH + tid],
                                 ew1l[130*HH + tid], ew1l[131*HH + tid]);
        s.B2[tid]  = eb2l[tid];
        s.FB1[tid] = fb1l[tid];
        s.FW2[tid] = fw2l[tid];
        s.Magg[tid] = 0.0f;
        s.T2i[tid]  = 0.0f;
    }
    if (tid < 2) s.Fxy[tid] = 0.0f;

    uint32_t aT1[2] = { smem_u32(s.T1h[0]), smem_u32(s.T1h[1]) };
    uint32_t aW2h = smem_u32(s.WB[0]), aW2l = smem_u32(s.WB[1]);
    uint32_t aF1  = smem_u32(s.WB[2]);

    float4 sti = ((const float4*)state)[b*NN + i];
    float spi  = sti.z*sti.z + sti.w*sti.w;
    float fb2v = fb2l[0];
    int jt_i = i >> 7, r_i = i & (JT - 1);

    float fx = 0.f, fy = 0.f;
    float cs[16];
    #pragma unroll
    for (int q = 0; q < 16; ++q) cs[q] = 0.f;

    // lane constants
    int rA0   = wm*32 + (lane & 7) + ((lane >> 3) & 1) * 8;   // A-frag row base
    int colA8 = ((lane >> 4) & 1) * 8;
    int krB   = (lane & 7) + ((lane >> 3) & 1) * 8;           // B-frag k row
    int ncB8  = ((lane >> 4) & 1) * 8;

    __syncthreads();   // (INIT)

    #pragma unroll 1
    for (int jt = 0; jt < NTILES; ++jt){
        int pb = jt & 1;
        // ================= stage 0: thread owns full row j (64 cols) =============
        {
            int jr = tid;
            int j = jt*JT + jr;
            float4 stj = ((const float4*)state)[b*NN + j];
            float dxp = stj.x - sti.x;
            float dyp = stj.y - sti.y;
            float dsq = dxp*dxp + dyp*dyp;
            float invd = rsqrtf(dsq + 1e-8f);
            float nx = dxp * invd;
            float ny = dyp * invd;
            float dvx = stj.z - sti.z;
            float dvy = stj.w - sti.w;
            float spj = stj.z*stj.z + stj.w*stj.w;
            float appr = dvx*nx + dvy*ny;
            s.Nx[pb][jr] = nx;
            s.Ny[pb][jr] = ny;

            __half* T1d = s.T1h[pb];
            #pragma unroll
            for (int c = 0; c < 8; ++c){
                uint32_t hibuf[4];
                #pragma unroll
                for (int q = 0; q < 4; ++q){
                    float tv[2];
                    #pragma unroll
                    for (int e = 0; e < 2; ++e){
                        int n = c*8 + q*2 + e;
                        float cc = g_ct[rb][(b*HH + n)*NN + j];
                        float4 w = s.WS[n];
                        float p = s.A[n] + cc;
                        p = fmaf(dsq,  w.x, p);
                        p = fmaf(spi,  w.y, p);
                        p = fmaf(spj,  w.z, p);
                        p = fmaf(appr, w.w, p);
                        tv[e] = silu_f(p);
                    }
                    hibuf[q] = packh2(tv[0], tv[1]);
                }
                uint32_t off = (uint32_t)(jr*128) + (((uint32_t)c ^ (uint32_t)(jr & 7)) << 4);
                *(uint4*)((char*)T1d + off) =
                    make_uint4(hibuf[0], hibuf[1], hibuf[2], hibuf[3]);
            }
        }
        __syncthreads();   // (A) only barrier per tile

        // ================= GEMM1: D1 = T1 @ (W2h + W2l), m32n64 ==================
        float acc[2][8][4];
        #pragma unroll
        for (int mt = 0; mt < 2; ++mt)
            #pragma unroll
            for (int q = 0; q < 8; ++q)
                #pragma unroll
                for (int p = 0; p < 4; ++p) acc[mt][q][p] = 0.f;
        #pragma unroll
        for (int kk = 0; kk < 4; ++kk){
            uint32_t a0[4], a1[4];
            ldsm4(a0[0],a0[1],a0[2],a0[3],
                  aT1[pb] + sw128((uint32_t)(rA0*128 + (kk*16 + colA8)*2)));
            ldsm4(a1[0],a1[1],a1[2],a1[3],
                  aT1[pb] + sw128((uint32_t)((rA0+16)*128 + (kk*16 + colA8)*2)));
            #pragma unroll
            for (int np = 0; np < 4; ++np){
                uint32_t boff = sw128((uint32_t)((kk*16 + krB)*128 + (np*16 + ncB8)*2));
                uint32_t bh0, bh1, bh2, bh3, bl0, bl1, bl2, bl3;
                ldsm4t(bh0, bh1, bh2, bh3, aW2h + boff);
                ldsm4t(bl0, bl1, bl2, bl3, aW2l + boff);
                mma16816(acc[0][np*2],   a0[0],a0[1],a0[2],a0[3], bh0, bh1);
                mma16816(acc[0][np*2+1], a0[0],a0[1],a0[2],a0[3], bh2, bh3);
                mma16816(acc[1][np*2],   a1[0],a1[1],a1[2],a1[3], bh0, bh1);
                mma16816(acc[1][np*2+1], a1[0],a1[1],a1[2],a1[3], bh2, bh3);
                mma16816(acc[0][np*2],   a0[0],a0[1],a0[2],a0[3], bl0, bl1);
                mma16816(acc[0][np*2+1], a0[0],a0[1],a0[2],a0[3], bl2, bl3);
                mma16816(acc[1][np*2],   a1[0],a1[1],a1[2],a1[3], bl0, bl1);
                mma16816(acc[1][np*2+1], a1[0],a1[1],a1[2],a1[3], bl2, bl3);
            }
        }

        // ---- epilogue1: silu(+b2), colsums, pack A-frags; row-i capture ---------
        uint32_t af[2][4][4];
        #pragma unroll
        for (int mt = 0; mt < 2; ++mt){
            #pragma unroll
            for (int nt = 0; nt < 8; ++nt){
                int c0 = nt*8 + (lane & 3)*2;
                float b2a = s.B2[c0], b2b = s.B2[c0+1];
                float v00 = silu_f(acc[mt][nt][0] + b2a);
                float v01 = silu_f(acc[mt][nt][1] + b2b);
                float v10 = silu_f(acc[mt][nt][2] + b2a);
                float v11 = silu_f(acc[mt][nt][3] + b2b);
                cs[nt*2]   += v00 + v10;
                cs[nt*2+1] += v01 + v11;
                int kk = nt >> 1;
                if ((nt & 1) == 0){
                    af[mt][kk][0] = packh2(v00, v01);
                    af[mt][kk][1] = packh2(v10, v11);
                } else {
                    af[mt][kk][2] = packh2(v00, v01);
                    af[mt][kk][3] = packh2(v10, v11);
                }
                if (jt == jt_i && wm == (r_i >> 5) && mt == ((r_i >> 4) & 1)){
                    int ri = r_i & 15;
                    if (ri < 8){
                        if ((lane >> 2) == ri){ s.T2i[c0] = v00; s.T2i[c0+1] = v01; }
                    } else {
                        if ((lane >> 2) == ri - 8){ s.T2i[c0] = v10; s.T2i[c0+1] = v11; }
                    }
                }
            }
        }

        // ================= GEMM2: D2 = T2(regs) @ F1, m32n64 =====================
        #pragma unroll
        for (int mt = 0; mt < 2; ++mt)
            #pragma unroll
            for (int q = 0; q < 8; ++q)
                #pragma unroll
                for (int p = 0; p < 4; ++p) acc[mt][q][p] = 0.f;
        #pragma unroll
        for (int kk = 0; kk < 4; ++kk){
            #pragma unroll
            for (int np = 0; np < 4; ++np){
                uint32_t boff = sw128((uint32_t)((kk*16 + krB)*128 + (np*16 + ncB8)*2));
                uint32_t f0, f1, f2, f3;
                ldsm4t(f0, f1, f2, f3, aF1 + boff);
                mma16816(acc[0][np*2],   af[0][kk][0], af[0][kk][1], af[0][kk][2], af[0][kk][3], f0, f1);
                mma16816(acc[0][np*2+1], af[0][kk][0], af[0][kk][1], af[0][kk][2], af[0][kk][3], f2, f3);
                mma16816(acc[1][np*2],   af[1][kk][0], af[1][kk][1], af[1][kk][2], af[1][kk][3], f0, f1);
                mma16816(acc[1][np*2+1], af[1][kk][0], af[1][kk][1], af[1][kk][2], af[1][kk][3], f2, f3);
            }
        }

        // ---- epilogue2: fw = silu(D2 + fb1) . fw2 + fb2; force -------------------
        #pragma unroll
        for (int mt = 0; mt < 2; ++mt){
            float pm = 0.f, pm8 = 0.f;
            #pragma unroll
            for (int nt = 0; nt < 8; ++nt){
                int c0 = nt*8 + (lane & 3)*2;
                float fa = s.FB1[c0], fb = s.FB1[c0+1];
                float wa = s.FW2[c0], wb = s.FW2[c0+1];
                pm  = fmaf(silu_f(acc[mt][nt][0] + fa), wa, pm);
                pm  = fmaf(silu_f(acc[mt][nt][1] + fb), wb, pm);
                pm8 = fmaf(silu_f(acc[mt][nt][2] + fa), wa, pm8);
                pm8 = fmaf(silu_f(acc[mt][nt][3] + fb), wb, pm8);
            }
            pm  += __shfl_xor_sync(0xffffffffu, pm, 1);
            pm  += __shfl_xor_sync(0xffffffffu, pm, 2);
            pm8 += __shfl_xor_sync(0xffffffffu, pm8, 1);
            pm8 += __shfl_xor_sync(0xffffffffu, pm8, 2);
            if ((lane & 3) == 0){
                int r0_ = wm*32 + mt*16 + (lane >> 2);
                int r1_ = r0_ + 8;
                float f0 = pm + fb2v, f1 = pm8 + fb2v;
                fx = fmaf(f0, s.Nx[pb][r0_], fx); fx = fmaf(f1, s.Nx[pb][r1_], fx);
                fy = fmaf(f0, s.Ny[pb][r0_], fy); fy = fmaf(f1, s.Ny[pb][r1_], fy);
            }
        }
        // no barrier: T1/Nx/Ny parity-buffered; next syncA orders reuse
    }

    // ---- final m_agg reduction ----
    #pragma unroll
    for (int nt = 0; nt < 8; ++nt){
        float s0 = cs[nt*2], s1 = cs[nt*2+1];
        s0 += __shfl_xor_sync(0xffffffffu, s0, 4);
        s0 += __shfl_xor_sync(0xffffffffu, s0, 8);
        s0 += __shfl_xor_sync(0xffffffffu, s0, 16);
        s1 += __shfl_xor_sync(0xffffffffu, s1, 4);
        s1 += __shfl_xor_sync(0xffffffffu, s1, 8);
        s1 += __shfl_xor_sync(0xffffffffu, s1, 16);
        if (lane < 4){
            int c0 = nt*8 + lane*2;
            atomicAdd(&s.Magg[c0],     s0);
            atomicAdd(&s.Magg[c0 + 1], s1);
        }
    }
    // ---- reduce forces (values at lanes lane&3==0) ----
    fx += __shfl_xor_sync(0xffffffffu, fx, 16);
    fx += __shfl_xor_sync(0xffffffffu, fx, 8);
    fx += __shfl_xor_sync(0xffffffffu, fx, 4);
    fy += __shfl_xor_sync(0xffffffffu, fy, 16);
    fy += __shfl_xor_sync(0xffffffffu, fy, 8);
    fy += __shfl_xor_sync(0xffffffffu, fy, 4);
    if (lane == 0){
        atomicAdd(&s.Fxy[0], fx);
        atomicAdd(&s.Fxy[1], fy);
    }
    __syncthreads();

    if (tid < 2){
        float v = s.Fxy[tid];
        if (accumulate) g_fsum[bi*2 + tid] += v;
        else            g_fsum[bi*2 + tid] = v;
    }

    // ================= fused node-update MLP (128 threads) =================
    float* sIn = (float*)s.T1h;      // T1 region dead
    float* sP  = sIn + 128;
    float* sY  = sP + 128;
    if (tid < 64) sIn[tid]      = g_h[bi*HH + tid];
    else          sIn[tid]      = s.Magg[tid - 64] - s.T2i[tid - 64];
    __syncthreads();
    {
        int out = tid & 63, chk = tid >> 6;
        float p = 0.f;
        #pragma unroll 8
        for (int k = 0; k < 64; ++k)
            p = fmaf(sIn[chk*64 + k], nw1l[(chk*64 + k)*HH + out], p);
        sP[tid] = p;
    }
    __syncthreads();
    if (tid < 64)
        sY[tid] = silu_x(sP[tid] + sP[tid+64] + nb1l[tid]);
    __syncthreads();
    {
        int out = tid & 63, chk = tid >> 6;
        float p = 0.f;
        #pragma unroll 8
        for (int k = 0; k < 32; ++k)
            p = fmaf(sY[chk*32 + k], nw2l[(chk*32 + k)*HH + out], p);
        sP[tid] = p;
    }
    __syncthreads();
    if (tid < 64){
        float hn = sP[tid] + sP[tid+64] + nb2l[tid];
        g_h[bi*HH + tid] = hn;
        sIn[tid] = hn;
    }
    __syncthreads();

    // ====== fused next-layer prep: writes rb^1 buffer ======
    if (prep_next){
        int out = tid & 63, which = tid >> 6;
        float a = which ? 0.f : eb1n[out];
        const float* w = ew1n + (which ? HH*HH : 0);
        #pragma unroll 8
        for (int k = 0; k < HH; ++k)
            a = fmaf(sIn[k], w[k*HH + out], a);
        if (which == 0) g_a[rb ^ 1][bi*HH + out] = a;
        else            g_ct[rb ^ 1][(b*HH + out)*NN + i] = a;
    }
}

// ---------------- wall MLP + output -----------------------------------------------
__global__ void k_final(const float* __restrict__ state,
                        const float* __restrict__ w1, const float* __restrict__ b1,
                        const float* __restrict__ w2, const float* __restrict__ b2,
                        const float* __restrict__ w3, const float* __restrict__ b3,
                        float* __restrict__ out){
    __shared__ float sH[HH + 4];
    __shared__ float sY[HH];
    __shared__ float sM[4];
    int node = blockIdx.x; int t = threadIdx.x;
    sH[t] = g_h[node*HH + t];
    if (t < 4){
        float4 st = ((const float4*)state)[node];
        float d = (t == 0) ? st.x : (t == 1) ? 1.0f - st.x
                : (t == 2) ? st.y : 1.0f - st.y;
        sH[HH + t] = d;
    }
    __syncthreads();
    float a1 = b1[t];
    #pragma unroll 4
    for (int k = 0; k < HH + 4; ++k) a1 = fmaf(sH[k], w1[k*HH + t], a1);
    sY[t] = silu_x(a1);
    __syncthreads();
    float a2 = b2[t];
    #pragma unroll 8
    for (int k = 0; k < HH; ++k) a2 = fmaf(sY[k], w2[k*HH + t], a2);
    __syncthreads();
    sY[t] = silu_x(a2);
    __syncthreads();
    if (t < 4){
        float m = b3[t];
        #pragma unroll 8
        for (int k = 0; k < HH; ++k) m = fmaf(sY[k], w3[k*4 + t], m);
        sM[t] = m;
    }
    __syncthreads();
    if (t < 2){
        float wf = (t == 0) ? (sM[0] - sM[1]) : (sM[2] - sM[3]);
        out[node*2 + t] = g_fsum[node*2 + t] + wf;
    }
}

// ---------------- launch ----------------------------------------------------------
extern "C" void kernel_launch(void* const* d_in, const int* in_sizes, int n_in,
                              void* d_out, int out_size){
    const float* state = (const float*)d_in[0];
    const float* hiw  = (const float*)d_in[1];
    const float* hib  = (const float*)d_in[2];
    const float* ew1  = (const float*)d_in[3];
    const float* eb1  = (const float*)d_in[4];
    const float* ew2  = (const float*)d_in[5];
    const float* eb2  = (const float*)d_in[6];
    const float* fw1  = (const float*)d_in[7];
    const float* fb1  = (const float*)d_in[8];
    const float* fw2  = (const float*)d_in[9];
    const float* fb2  = (const float*)d_in[10];
    const float* nw1  = (const float*)d_in[11];
    const float* nb1  = (const float*)d_in[12];
    const float* nw2  = (const float*)d_in[13];
    const float* nb2  = (const float*)d_in[14];
    const float* ww1  = (const float*)d_in[15];
    const float* wb1  = (const float*)d_in[16];
    const float* ww2  = (const float*)d_in[17];
    const float* wb2  = (const float*)d_in[18];
    const float* ww3  = (const float*)d_in[19];
    const float* wb3  = (const float*)d_in[20];
    float* out = (float*)d_out;

    int smem = (int)sizeof(EdgeSmem);
    cudaFuncSetAttribute(k_edge, cudaFuncAttributeMaxDynamicSharedMemorySize, smem);

    k_wprep<<<6, 256>>>(ew2, fw1);
    k_pre<<<NODES, HH>>>(state, hiw, hib, ew1, eb1);
    for (int l = 0; l < 3; ++l){
        int pn = (l < 2) ? 1 : 0;
        const float* ew1n = ew1 + (pn ? (l+1)*132*HH : 0);
        const float* eb1n = eb1 + (pn ? (l+1)*HH : 0);
        k_edge<<<NODES, 128, smem>>>(state,
                               ew1 + l*132*HH,
                               eb2 + l*HH,
                               fb1 + l*HH,
                               fw2 + l*HH,
                               fb2 + l,
                               nw1 + l*2*HH*HH, nb1 + l*HH,
                               nw2 + l*HH*HH,   nb2 + l*HH,
                               ew1n, eb1n,
                               l, l, pn);
    }
    k_final<<<NODES, HH>>>(state, ww1, wb1, ww2, wb2, ww3, wb3, out);
}